// round 2
// baseline (speedup 1.0000x reference)
#include <cuda_runtime.h>

// LSTM_3444563771996 : I=28, H=64, T=128, B=4096, OUT=10
// Persistent per-CTA LSTM over T with unified [x;h] K=92 GEMM per step.

#define TI     128   // timesteps
#define II     28    // input dim
#define HH     64    // hidden dim
#define GG     256   // 4H gates
#define KK     92    // I + H
#define BB     4096  // batch
#define OUTD   10
#define MB     32    // batch rows per CTA
#define NTHR   256
#define ASTR   36    // padded row stride for A (k-major [KK][ASTR])

#define SM_W_FLOATS (KK * GG)      // 23552
#define SM_A_FLOATS (KK * ASTR)    // 3312
#define SM_G_FLOATS (MB * GG)      // 8192
#define SMEM_BYTES  ((SM_W_FLOATS + SM_A_FLOATS + SM_G_FLOATS) * 4)  // 140224

__device__ __forceinline__ float sigm_(float v) {
    return __fdividef(1.0f, 1.0f + __expf(-v));
}
__device__ __forceinline__ float tanh_(float v) {
    float e = __expf(-2.0f * v);
    return __fdividef(2.0f, 1.0f + e) - 1.0f;
}

__global__ __launch_bounds__(NTHR, 1)
void lstm_kernel(const float* __restrict__ x,
                 const float* __restrict__ W_ih, const float* __restrict__ W_hh,
                 const float* __restrict__ b_ih, const float* __restrict__ b_hh,
                 const float* __restrict__ W_out, const float* __restrict__ b_out,
                 float* __restrict__ out)
{
    extern __shared__ float sm[];
    float* Wsm = sm;                         // [KK][GG]  k-major weights [W_ih|W_hh]^T
    float* Asm = sm + SM_W_FLOATS;           // [KK][ASTR] activations: k<28 -> x_t, k>=28 -> h
    float* Gsm = Asm + SM_A_FLOATS;          // [MB][GG]  gate preacts (row-major)

    const int tid = threadIdx.x;
    const int b0  = blockIdx.x * MB;

    // ---- load weights transposed to k-major ----
    for (int idx = tid; idx < KK * GG; idx += NTHR) {
        int k = idx >> 8;        // / GG
        int g = idx & (GG - 1);
        Wsm[idx] = (k < II) ? W_ih[g * II + k] : W_hh[g * HH + (k - II)];
    }
    // ---- zero A (h starts at 0) ----
    for (int idx = tid; idx < KK * ASTR; idx += NTHR) Asm[idx] = 0.0f;

    const int gc = tid & 63;        // gate column group
    const int rg = tid >> 6;        // row group 0..3
    const int g0 = gc * 4;          // 4 gates per thread
    const int r0 = rg * 8;          // 8 rows per thread
    const int u  = tid & 63;        // hidden unit for activation phase

    // combined bias, kept in registers
    float4 bias;
    bias.x = b_ih[g0 + 0] + b_hh[g0 + 0];
    bias.y = b_ih[g0 + 1] + b_hh[g0 + 1];
    bias.z = b_ih[g0 + 2] + b_hh[g0 + 2];
    bias.w = b_ih[g0 + 3] + b_hh[g0 + 3];

    float c[8];
#pragma unroll
    for (int r = 0; r < 8; ++r) c[r] = 0.0f;

    __syncthreads();

    for (int t = 0; t < TI; ++t) {
        // ---- stage x_t transposed into Asm[0..27][row] ----
        if (tid < MB * 7) {
            int row = tid / 7;
            int seg = tid - row * 7;
            const float4 xv = *reinterpret_cast<const float4*>(
                x + ((size_t)(b0 + row) * TI + t) * II + seg * 4);
            int ka = seg * 4;
            Asm[(ka + 0) * ASTR + row] = xv.x;
            Asm[(ka + 1) * ASTR + row] = xv.y;
            Asm[(ka + 2) * ASTR + row] = xv.z;
            Asm[(ka + 3) * ASTR + row] = xv.w;
        }
        __syncthreads();   // x_t and h(t-1) ready

        // ---- GEMM: gates[256 x 32] = W[256 x 92] * A[92 x 32] + b ----
        float acc[4][8];
#pragma unroll
        for (int r = 0; r < 8; ++r) {
            acc[0][r] = bias.x; acc[1][r] = bias.y;
            acc[2][r] = bias.z; acc[3][r] = bias.w;
        }

#pragma unroll 4
        for (int k = 0; k < KK; ++k) {
            const float4 w  = *reinterpret_cast<const float4*>(&Wsm[k * GG + g0]);
            const float4 a0 = *reinterpret_cast<const float4*>(&Asm[k * ASTR + r0]);
            const float4 a1 = *reinterpret_cast<const float4*>(&Asm[k * ASTR + r0 + 4]);
            const float wv[4] = {w.x, w.y, w.z, w.w};
            const float av[8] = {a0.x, a0.y, a0.z, a0.w, a1.x, a1.y, a1.z, a1.w};
#pragma unroll
            for (int gi = 0; gi < 4; ++gi)
#pragma unroll
                for (int r = 0; r < 8; ++r)
                    acc[gi][r] = fmaf(wv[gi], av[r], acc[gi][r]);
        }

        // ---- store preacts row-major (conflict-free STS.128) ----
#pragma unroll
        for (int r = 0; r < 8; ++r) {
            float4 v = make_float4(acc[0][r], acc[1][r], acc[2][r], acc[3][r]);
            *reinterpret_cast<float4*>(&Gsm[(r0 + r) * GG + g0]) = v;
        }
        __syncthreads();   // preacts visible; GEMM reads of A complete

        // ---- activations + state update; write h into A's k>=28 rows ----
#pragma unroll
        for (int r = 0; r < 8; ++r) {
            const int row = r0 + r;
            const float* gr = &Gsm[row * GG];
            float ig = sigm_(gr[u]);
            float fg = sigm_(gr[u + 64]);
            float gg = tanh_(gr[u + 128]);
            float og = sigm_(gr[u + 192]);
            float cv = fmaf(fg, c[r], ig * gg);
            c[r] = cv;
            Asm[(II + u) * ASTR + row] = og * tanh_(cv);
        }
        // next iteration's top sync orders h writes before the next GEMM;
        // x-stage writes touch disjoint k<28 rows.
    }

    // ---- final linear: out = h_T @ W_out^T + b_out ----
    __syncthreads();                    // all h writes complete
    for (int idx = tid; idx < OUTD * HH; idx += NTHR) Gsm[idx] = W_out[idx];
    if (tid < OUTD) Gsm[OUTD * HH + tid] = b_out[tid];
    __syncthreads();

    for (int cell = tid; cell < MB * OUTD; cell += NTHR) {
        int row = cell / OUTD;
        int o   = cell - row * OUTD;
        float s = Gsm[OUTD * HH + o];
#pragma unroll
        for (int j = 0; j < HH; ++j)
            s = fmaf(Asm[(II + j) * ASTR + row], Gsm[o * HH + j], s);
        out[(size_t)(b0 + row) * OUTD + o] = s;
    }
}

extern "C" void kernel_launch(void* const* d_in, const int* in_sizes, int n_in,
                              void* d_out, int out_size)
{
    const float* x     = (const float*)d_in[0];
    const float* W_ih  = (const float*)d_in[1];
    const float* W_hh  = (const float*)d_in[2];
    const float* b_ih  = (const float*)d_in[3];
    const float* b_hh  = (const float*)d_in[4];
    const float* W_out = (const float*)d_in[5];
    const float* b_out = (const float*)d_in[6];
    float* out = (float*)d_out;

    cudaFuncSetAttribute(lstm_kernel,
                         cudaFuncAttributeMaxDynamicSharedMemorySize, SMEM_BYTES);
    lstm_kernel<<<BB / MB, NTHR, SMEM_BYTES>>>(x, W_ih, W_hh, b_ih, b_hh,
                                               W_out, b_out, out);
}